// round 5
// baseline (speedup 1.0000x reference)
#include <cuda_runtime.h>
#include <cstdint>

#define F_FEAT 4096
#define HID    128
#define OUT3H  384      // 3*HID
#define IN_DIM 129      // HID + 1
#define BOUNDARY_V (-0.01f)

// Cross-feature reduction scratch. Static zero-init; the epilogue block
// resets everything after consuming, so every graph replay starts identical.
__device__ float        g_C_acc[HID];
__device__ float        g_H_acc[HID];
__device__ unsigned int g_cnt_masked;
__device__ unsigned int g_done;

__device__ __forceinline__ float sigmoidf(float x) {
    return 1.0f / (1.0f + expf(-x));
}

__device__ __forceinline__ bool mask_at(const void* mptr, int f, int mode) {
    if (mode == 0)      return ((const unsigned char*)mptr)[f] != 0;
    else if (mode == 1) return ((const int*)mptr)[f] != 0;
    else                return ((const float*)mptr)[f] != 0.0f;
}

// ---------------------------------------------------------------------------
// Fused kernel: one feature per block, 384 threads = 12 warps.
//  0) per-block mask dtype detection (first 4096 bytes, L2-resident)
//  1) batched mat-vec: warp handles 4 consecutive rows per step as one
//     16B-aligned contiguous chunk of 129 float4s (aligned LDG.128 stream)
//  2) gate math on threads 0..127, write H_curr, atomic accumulate
//  3) last block: finalize C_curr + MLP head + softmax, reset scratch
// ---------------------------------------------------------------------------
__global__ __launch_bounds__(384, 4) void fused_kernel(
    const int*           __restrict__ tim,
    const float*         __restrict__ X,
    const void*          __restrict__ maskp,
    const float*         __restrict__ Ht,
    const int*           __restrict__ last_occured,
    const float*         __restrict__ c_t,
    const float*         __restrict__ Wl,    // (F, 384, 129)
    const float*         __restrict__ bl,    // (F, 384)
    const float*         __restrict__ xTw,   // (F, 256)
    const float*         __restrict__ xTb,   // (F, 256)
    const float*         __restrict__ dTw,   // (F, 384)
    const float*         __restrict__ ciw,   // (F, 128)
    const float*         __restrict__ cow,   // (F, 128)
    const float*         __restrict__ w1,    // (256, 256)
    const float*         __restrict__ b1,    // (256,)
    const float*         __restrict__ w2,    // (2, 256)
    const float*         __restrict__ b2,    // (2,)
    float*               __restrict__ out)   // full d_out
{
    const int f    = blockIdx.x;
    const int tid  = threadIdx.x;
    const int lane = tid & 31;
    const int warp = tid >> 5;

    __shared__ float s_inp[IN_DIM];
    __shared__ __align__(16) float s_shift[4][132];   // s_shift[i][j] = s_inp[j-i], 0 if j<i
    __shared__ float s_out[OUT3H];
    __shared__ int   s_comb;
    __shared__ int   s_islast;
    __shared__ float s_feat[256];
    __shared__ float s_h1[256];

    float* __restrict__ outH = out + 2;           // (F, 128)

    // --- 0) mask dtype detection over first F_FEAT bytes (as uint32) ---
    if (tid == 0) s_comb = 0;
    __syncthreads();
    {
        const uint32_t* mw = (const uint32_t*)maskp;
        int gt1 = 0, offnz = 0;
        #pragma unroll
        for (int i = tid; i < F_FEAT / 4; i += 384) {
            uint32_t w = mw[i];
            gt1   |= ((w & 0xFEFEFEFEu) != 0u) ? 1 : 0;   // any byte > 1
            offnz |= ((w & 0xFFFFFF00u) != 0u) ? 1 : 0;   // nonzero off-stride byte
        }
        int comb = (gt1 << 1) | offnz;
        #pragma unroll
        for (int o = 16; o > 0; o >>= 1)
            comb |= __shfl_xor_sync(0xffffffffu, comb, o);
        if (lane == 0 && comb) atomicOr(&s_comb, comb);
    }

    // --- 1a) stage input vector [X[f], Ht[f,:]] and bias (coalesced) ---
    if (tid < IN_DIM)
        s_inp[tid] = (tid == 0) ? X[f] : Ht[(size_t)f * HID + (tid - 1)];
    s_out[tid] = bl[(size_t)f * OUT3H + tid];
    __syncthreads();

    // --- 1b) build shifted input copies for aligned dot4 ---
    for (int idx = tid; idx < 4 * 132; idx += 384) {
        const int i  = idx >> 7 ;        // idx / 132? careful: use div
        const int ii = idx / 132;
        const int jj = idx - ii * 132;
        const int src = jj - ii;
        s_shift[ii][jj] = (src >= 0 && src <= 128) ? s_inp[src] : 0.0f;
        (void)i;
    }
    __syncthreads();

    const int c = s_comb;
    const int mode = (c & 2) ? 2 : ((c & 1) ? 0 : 1);  // 2=f32, 0=u8, 1=i32
    const bool m = mask_at(maskp, f, mode);

    const float* __restrict__ Wf = Wl + (size_t)f * OUT3H * IN_DIM;
    const int rbase = warp * 32;

    // 8 chunks of 4 rows each; chunk = 129 contiguous, 16B-aligned float4s.
    #pragma unroll 2
    for (int j = 0; j < 8; j++) {
        const int r0 = rbase + 4 * j;
        const float4* __restrict__ cbase =
            (const float4*)(Wf + (size_t)r0 * IN_DIM);

        float a0 = 0.0f, a1 = 0.0f, a2 = 0.0f, a3 = 0.0f;

        // i = 0 : all lanes row 0, cols 4l..4l+3
        {
            const float4 v = cbase[lane];
            const float4 u = *(const float4*)&s_shift[0][4 * lane];
            a0 += v.x * u.x + v.y * u.y + v.z * u.z + v.w * u.w;
        }
        // i = 1..3 : lanes>=1 entirely in row i (cols 4l+k-i); lane 0 straddles.
        {
            const float4 v = cbase[32 + lane];
            const float4 u = *(const float4*)&s_shift[1][4 * lane];
            a1 += v.x * u.x + v.y * u.y + v.z * u.z + v.w * u.w;
            if (lane == 0) a0 += v.x * s_inp[128];
        }
        {
            const float4 v = cbase[64 + lane];
            const float4 u = *(const float4*)&s_shift[2][4 * lane];
            a2 += v.x * u.x + v.y * u.y + v.z * u.z + v.w * u.w;
            if (lane == 0) a1 += v.x * s_inp[127] + v.y * s_inp[128];
        }
        {
            const float4 v = cbase[96 + lane];
            const float4 u = *(const float4*)&s_shift[3][4 * lane];
            a3 += v.x * u.x + v.y * u.y + v.z * u.z + v.w * u.w;
            if (lane == 0) a2 += v.x * s_inp[126] + v.y * s_inp[127] + v.z * s_inp[128];
        }
        // tail float4 q=128: row 3, cols 125..128 (lane 31 for balance)
        if (lane == 31) {
            const float4 v = cbase[128];
            a3 += v.x * s_inp[125] + v.y * s_inp[126] + v.z * s_inp[127] + v.w * s_inp[128];
        }

        // reduce the 4 row-accumulators across the warp
        float accs[4] = {a0, a1, a2, a3};
        #pragma unroll
        for (int rr = 0; rr < 4; rr++) {
            float acc = accs[rr];
            #pragma unroll
            for (int o = 16; o > 0; o >>= 1)
                acc += __shfl_xor_sync(0xffffffffu, acc, o);
            if (lane == 0) s_out[r0 + rr] += acc;
        }
    }
    __syncthreads();

    // --- 2) gate math on threads 0..127 ---
    if (tid < HID) {
        const int t = tid;
        const float gi_pre = s_out[t];
        const float go_pre = s_out[HID + t];
        const float gc_pre = s_out[2 * HID + t];

        const float x     = s_inp[0];
        const float delta = (float)(tim[0] - last_occured[f]);

        const size_t f256 = (size_t)f * 256;
        const size_t f384 = (size_t)f * 384;
        const size_t f128 = (size_t)f * 128;

        const float xm1 = xTw[f256 + t]       * x + xTb[f256 + t];
        const float xm2 = xTw[f256 + HID + t] * x + xTb[f256 + HID + t];

        const float wd1 = dTw[f384 + t];
        float       wd2 = dTw[f384 + HID + t];
        if (t == 0) wd2 = fminf(wd2, BOUNDARY_V);   // clamp hits flat row H=128 only
        const float wdo = dTw[f384 + 2 * HID + t];

        const float T1 = sigmoidf(xm1 + sigmoidf(wd1 * delta));
        const float T2 = sigmoidf(xm2 + sigmoidf(wd2 * delta));

        const float ctv = c_t[t];
        const float gi  = sigmoidf(gi_pre + ciw[f128 + t] * ctv);
        const float gc  = tanhf(gc_pre);

        const float giT1    = gi * T1;
        const float c_tilde = (1.0f - giT1) * ctv + giT1 * gc;
        const float c_new   = (1.0f - gi)   * ctv + gi * T2 * gc;
        const float go      = sigmoidf(go_pre + cow[f128 + t] * c_tilde + wdo * delta);

        const float Hc = m ? (go * tanhf(c_tilde)) : 0.0f;

        outH[f128 + t] = Hc;     // any==0 fallback patched by epilogue (degenerate)

        if (m) {
            atomicAdd(&g_C_acc[t], c_new);
            atomicAdd(&g_H_acc[t], Hc);
            if (t == 0) atomicAdd(&g_cnt_masked, 1u);
        }
    }

    // --- 3) last-block epilogue ---
    __threadfence();
    __syncthreads();
    if (tid == 0) {
        unsigned int old = atomicAdd(&g_done, 1u);
        s_islast = (old == (unsigned int)(F_FEAT - 1)) ? 1 : 0;
    }
    __syncthreads();
    if (!s_islast) return;

    __threadfence();   // acquire all other blocks' accumulator writes

    const unsigned int cnt = g_cnt_masked;
    const float cntf = fmaxf((float)cnt, 1.0f);

    if (cnt == 0) {
        // Degenerate mask.any()==0 case: H_curr = Ht. Rewrite output.
        for (int i = tid; i < F_FEAT * HID; i += 384)
            outH[i] = Ht[i];
    }

    if (tid < HID) {
        const float Cc = g_C_acc[tid] / cntf;
        s_feat[tid]       = Cc;
        s_feat[HID + tid] = g_H_acc[tid] / cntf;
        out[2 + (size_t)F_FEAT * HID + tid] = Cc;   // C_curr output
        // reset scratch for the next graph replay
        g_C_acc[tid] = 0.0f;
        g_H_acc[tid] = 0.0f;
    }
    if (tid == 0) { g_cnt_masked = 0u; g_done = 0u; }
    __syncthreads();

    if (tid < 256) {
        float acc = b1[tid];
        #pragma unroll 8
        for (int i = 0; i < 256; i++)
            acc += w1[tid * 256 + i] * s_feat[i];
        s_h1[tid] = fmaxf(acc, 0.0f);
    }
    __syncthreads();

    if (tid < 32) {
        float a0 = 0.0f, a1 = 0.0f;
        #pragma unroll
        for (int k = tid; k < 256; k += 32) {
            const float h = s_h1[k];
            a0 += w2[k]       * h;
            a1 += w2[256 + k] * h;
        }
        #pragma unroll
        for (int o = 16; o > 0; o >>= 1) {
            a0 += __shfl_xor_sync(0xffffffffu, a0, o);
            a1 += __shfl_xor_sync(0xffffffffu, a1, o);
        }
        if (tid == 0) {
            const float l0 = a0 + b2[0];
            const float l1 = a1 + b2[1];
            const float mx = fmaxf(l0, l1);
            const float e0 = expf(l0 - mx);
            const float e1 = expf(l1 - mx);
            const float s  = e0 + e1;
            out[0] = e0 / s;
            out[1] = e1 / s;
        }
    }
}

// ---------------------------------------------------------------------------
// Launch
// ---------------------------------------------------------------------------
extern "C" void kernel_launch(void* const* d_in, const int* in_sizes, int n_in,
                              void* d_out, int out_size) {
    const int*   tim   = (const int*)  d_in[0];
    const float* X     = (const float*)d_in[1];
    // d_in[2] = X_hap (unused by reference)
    const void*  maskp = (const void*) d_in[3];
    const float* Ht    = (const float*)d_in[4];
    // d_in[5] = Ct (unused by reference)
    const int*   lastoc= (const int*)  d_in[6];
    const float* c_t   = (const float*)d_in[7];
    const float* Wl    = (const float*)d_in[8];
    const float* bl    = (const float*)d_in[9];
    const float* xTw   = (const float*)d_in[10];
    const float* xTb   = (const float*)d_in[11];
    const float* dTw   = (const float*)d_in[12];
    const float* ciw   = (const float*)d_in[13];
    const float* cow   = (const float*)d_in[14];
    const float* w1    = (const float*)d_in[15];
    const float* b1    = (const float*)d_in[16];
    const float* w2    = (const float*)d_in[17];
    const float* b2    = (const float*)d_in[18];

    fused_kernel<<<F_FEAT, 384>>>(tim, X, maskp, Ht, lastoc, c_t,
                                  Wl, bl, xTw, xTb, dTw, ciw, cow,
                                  w1, b1, w2, b2, (float*)d_out);
}

// round 6
// speedup vs baseline: 1.1634x; 1.1634x over previous
#include <cuda_runtime.h>
#include <cstdint>

#define F_FEAT 4096
#define HID    128
#define OUT3H  384      // 3*HID
#define IN_DIM 129      // HID + 1
#define BOUNDARY_V (-0.01f)

// Cross-feature reduction scratch. Static zero-init; the epilogue block
// resets everything after consuming, so every graph replay starts identical.
__device__ float        g_C_acc[HID];
__device__ float        g_H_acc[HID];
__device__ unsigned int g_cnt_masked;
__device__ unsigned int g_done;

__device__ __forceinline__ float sigmoidf(float x) {
    return 1.0f / (1.0f + expf(-x));
}

__device__ __forceinline__ bool mask_at(const void* mptr, int f, int mode) {
    if (mode == 0)      return ((const unsigned char*)mptr)[f] != 0;
    else if (mode == 1) return ((const int*)mptr)[f] != 0;
    else                return ((const float*)mptr)[f] != 0.0f;
}

// ---------------------------------------------------------------------------
// Fused kernel: one feature per block, 384 threads = 12 warps.
//  0) per-block mask dtype detection (first 4096 bytes, L2-resident)
//  1) batched mat-vec: warp-per-row lane-strided loads; inner loop has NO
//     reduction tree — one shfl_xor(16) + half-warp STS of partials; a
//     separate pass reduces 16 partials per row. Maximizes load batching.
//  2) gate math on threads 0..127, write H_curr, atomic accumulate
//  3) last block: finalize C_curr + MLP head + softmax, reset scratch
// ---------------------------------------------------------------------------
__global__ __launch_bounds__(384, 4) void fused_kernel(
    const int*           __restrict__ tim,
    const float*         __restrict__ X,
    const void*          __restrict__ maskp,
    const float*         __restrict__ Ht,
    const int*           __restrict__ last_occured,
    const float*         __restrict__ c_t,
    const float*         __restrict__ Wl,    // (F, 384, 129)
    const float*         __restrict__ bl,    // (F, 384)
    const float*         __restrict__ xTw,   // (F, 256)
    const float*         __restrict__ xTb,   // (F, 256)
    const float*         __restrict__ dTw,   // (F, 384)
    const float*         __restrict__ ciw,   // (F, 128)
    const float*         __restrict__ cow,   // (F, 128)
    const float*         __restrict__ w1,    // (256, 256)
    const float*         __restrict__ b1,    // (256,)
    const float*         __restrict__ w2,    // (2, 256)
    const float*         __restrict__ b2,    // (2,)
    float*               __restrict__ out)   // full d_out
{
    const int f    = blockIdx.x;
    const int tid  = threadIdx.x;
    const int lane = tid & 31;
    const int warp = tid >> 5;

    __shared__ float s_inp[IN_DIM];
    __shared__ float s_part[12][32][17];   // [warp][row-in-warp][half-lane], pad 17
    __shared__ float s_out[OUT3H];
    __shared__ int   s_comb;
    __shared__ int   s_islast;
    __shared__ float s_feat[256];
    __shared__ float s_h1[256];

    float* __restrict__ outH = out + 2;           // (F, 128)

    // --- 0) mask dtype detection over first F_FEAT bytes (as uint32) ---
    if (tid == 0) s_comb = 0;
    __syncthreads();
    {
        const uint32_t* mw = (const uint32_t*)maskp;
        int gt1 = 0, offnz = 0;
        #pragma unroll
        for (int i = tid; i < F_FEAT / 4; i += 384) {
            uint32_t w = mw[i];
            gt1   |= ((w & 0xFEFEFEFEu) != 0u) ? 1 : 0;   // any byte > 1
            offnz |= ((w & 0xFFFFFF00u) != 0u) ? 1 : 0;   // nonzero off-stride byte
        }
        int comb = (gt1 << 1) | offnz;
        #pragma unroll
        for (int o = 16; o > 0; o >>= 1)
            comb |= __shfl_xor_sync(0xffffffffu, comb, o);
        if (lane == 0 && comb) atomicOr(&s_comb, comb);
    }

    // --- 1a) stage input vector [X[f], Ht[f,:]] (coalesced) ---
    if (tid < IN_DIM)
        s_inp[tid] = (tid == 0) ? X[f] : Ht[(size_t)f * HID + (tid - 1)];
    __syncthreads();

    const int c = s_comb;
    const int mode = (c & 2) ? 2 : ((c & 1) ? 0 : 1);  // 2=f32, 0=u8, 1=i32
    const bool m = mask_at(maskp, f, mode);

    // Per-lane input registers (reused across all 32 rows this warp owns).
    const float in0 = s_inp[lane];
    const float in1 = s_inp[32 + lane];
    const float in2 = s_inp[64 + lane];
    const float in3 = s_inp[96 + lane];
    const float in4 = s_inp[128];

    const float* __restrict__ Wf = Wl + (size_t)f * OUT3H * IN_DIM;
    const int rbase = warp * 32;

    // --- 1b) load loop: rows independent, no reduction tree inside ---
    #pragma unroll 8
    for (int j = 0; j < 32; j++) {
        const float* __restrict__ wr = Wf + (size_t)(rbase + j) * IN_DIM;
        float acc = wr[lane]       * in0
                  + wr[32 + lane]  * in1
                  + wr[64 + lane]  * in2
                  + wr[96 + lane]  * in3;
        if (lane == 0) acc += wr[128] * in4;
        acc += __shfl_xor_sync(0xffffffffu, acc, 16);
        if (lane < 16) s_part[warp][j][lane] = acc;
    }
    __syncthreads();

    // --- 1c) reduction pass: thread t reduces row t (+ bias) ---
    {
        const int w = tid >> 5;
        const int j = tid & 31;
        float acc = bl[(size_t)f * OUT3H + tid];
        #pragma unroll
        for (int k = 0; k < 16; k++)
            acc += s_part[w][j][k];
        s_out[tid] = acc;
    }
    __syncthreads();

    // --- 2) gate math on threads 0..127 ---
    if (tid < HID) {
        const int t = tid;
        const float gi_pre = s_out[t];
        const float go_pre = s_out[HID + t];
        const float gc_pre = s_out[2 * HID + t];

        const float x     = s_inp[0];
        const float delta = (float)(tim[0] - last_occured[f]);

        const size_t f256 = (size_t)f * 256;
        const size_t f384 = (size_t)f * 384;
        const size_t f128 = (size_t)f * 128;

        const float xm1 = xTw[f256 + t]       * x + xTb[f256 + t];
        const float xm2 = xTw[f256 + HID + t] * x + xTb[f256 + HID + t];

        const float wd1 = dTw[f384 + t];
        float       wd2 = dTw[f384 + HID + t];
        if (t == 0) wd2 = fminf(wd2, BOUNDARY_V);   // clamp hits flat row H=128 only
        const float wdo = dTw[f384 + 2 * HID + t];

        const float T1 = sigmoidf(xm1 + sigmoidf(wd1 * delta));
        const float T2 = sigmoidf(xm2 + sigmoidf(wd2 * delta));

        const float ctv = c_t[t];
        const float gi  = sigmoidf(gi_pre + ciw[f128 + t] * ctv);
        const float gc  = tanhf(gc_pre);

        const float giT1    = gi * T1;
        const float c_tilde = (1.0f - giT1) * ctv + giT1 * gc;
        const float c_new   = (1.0f - gi)   * ctv + gi * T2 * gc;
        const float go      = sigmoidf(go_pre + cow[f128 + t] * c_tilde + wdo * delta);

        const float Hc = m ? (go * tanhf(c_tilde)) : 0.0f;

        outH[f128 + t] = Hc;     // any==0 fallback patched by epilogue (degenerate)

        if (m) {
            atomicAdd(&g_C_acc[t], c_new);
            atomicAdd(&g_H_acc[t], Hc);
            if (t == 0) atomicAdd(&g_cnt_masked, 1u);
        }
    }

    // --- 3) last-block epilogue ---
    __threadfence();
    __syncthreads();
    if (tid == 0) {
        unsigned int old = atomicAdd(&g_done, 1u);
        s_islast = (old == (unsigned int)(F_FEAT - 1)) ? 1 : 0;
    }
    __syncthreads();
    if (!s_islast) return;

    __threadfence();   // acquire all other blocks' accumulator writes

    const unsigned int cnt = g_cnt_masked;
    const float cntf = fmaxf((float)cnt, 1.0f);

    if (cnt == 0) {
        // Degenerate mask.any()==0 case: H_curr = Ht. Rewrite output.
        for (int i = tid; i < F_FEAT * HID; i += 384)
            outH[i] = Ht[i];
    }

    if (tid < HID) {
        const float Cc = g_C_acc[tid] / cntf;
        s_feat[tid]       = Cc;
        s_feat[HID + tid] = g_H_acc[tid] / cntf;
        out[2 + (size_t)F_FEAT * HID + tid] = Cc;   // C_curr output
        // reset scratch for the next graph replay
        g_C_acc[tid] = 0.0f;
        g_H_acc[tid] = 0.0f;
    }
    if (tid == 0) { g_cnt_masked = 0u; g_done = 0u; }
    __syncthreads();

    if (tid < 256) {
        float acc = b1[tid];
        #pragma unroll 8
        for (int i = 0; i < 256; i++)
            acc += w1[tid * 256 + i] * s_feat[i];
        s_h1[tid] = fmaxf(acc, 0.0f);
    }
    __syncthreads();

    if (tid < 32) {
        float a0 = 0.0f, a1 = 0.0f;
        #pragma unroll
        for (int k = tid; k < 256; k += 32) {
            const float h = s_h1[k];
            a0 += w2[k]       * h;
            a1 += w2[256 + k] * h;
        }
        #pragma unroll
        for (int o = 16; o > 0; o >>= 1) {
            a0 += __shfl_xor_sync(0xffffffffu, a0, o);
            a1 += __shfl_xor_sync(0xffffffffu, a1, o);
        }
        if (tid == 0) {
            const float l0 = a0 + b2[0];
            const float l1 = a1 + b2[1];
            const float mx = fmaxf(l0, l1);
            const float e0 = expf(l0 - mx);
            const float e1 = expf(l1 - mx);
            const float s  = e0 + e1;
            out[0] = e0 / s;
            out[1] = e1 / s;
        }
    }
}

// ---------------------------------------------------------------------------
// Launch
// ---------------------------------------------------------------------------
extern "C" void kernel_launch(void* const* d_in, const int* in_sizes, int n_in,
                              void* d_out, int out_size) {
    const int*   tim   = (const int*)  d_in[0];
    const float* X     = (const float*)d_in[1];
    // d_in[2] = X_hap (unused by reference)
    const void*  maskp = (const void*) d_in[3];
    const float* Ht    = (const float*)d_in[4];
    // d_in[5] = Ct (unused by reference)
    const int*   lastoc= (const int*)  d_in[6];
    const float* c_t   = (const float*)d_in[7];
    const float* Wl    = (const float*)d_in[8];
    const float* bl    = (const float*)d_in[9];
    const float* xTw   = (const float*)d_in[10];
    const float* xTb   = (const float*)d_in[11];
    const float* dTw   = (const float*)d_in[12];
    const float* ciw   = (const float*)d_in[13];
    const float* cow   = (const float*)d_in[14];
    const float* w1    = (const float*)d_in[15];
    const float* b1    = (const float*)d_in[16];
    const float* w2    = (const float*)d_in[17];
    const float* b2    = (const float*)d_in[18];

    fused_kernel<<<F_FEAT, 384>>>(tim, X, maskp, Ht, lastoc, c_t,
                                  Wl, bl, xTw, xTb, dTw, ciw, cow,
                                  w1, b1, w2, b2, (float*)d_out);
}